// round 7
// baseline (speedup 1.0000x reference)
#include <cuda_runtime.h>
#include <cuda_bf16.h>
#include <math.h>

// ---------------------------------------------------------------------------
// 3x exact top-K over columns of A (N x 2), (value desc, index asc) = lax.top_k.
// 5-launch pipeline:
//   H: chip-wide 65536-bin histograms of fkey(v), fkey(vo)   (1 elem/thread)
//   P: 2 blocks: per-bin output-offset tables g_base[sel][bin], threshold bins
//      g_bin[3], and a worklist of contributing segments {sel,bin,start,cnt}
//   C: scatter candidates to their final SEGMENT via atomicAdd(g_base)
//   B: one block per worklist segment: rank-by-comparison (keys unique), write
//      g_idx[start + rank] directly.
//   G: gather h rows, 512->2 GEMV (W in smem), softmax(2); preamble zeroes
//      g_hist/g_nwork for the next graph replay (g_base/g_bin rewritten by P).
// Output (float32, 15K): [0,3K) labels | [3K,9K) logits | [9K,15K) softmax
// ---------------------------------------------------------------------------

#define NBINS   65536
#define SHIFT   16
#define CAP     4096
#define KMAX    2048
#define SEGB    512               // max keys ranked per segment (smem 4KB)
#define WLCAP   8192
#define PICK_T  1024
#define PBPT    (NBINS / PICK_T)  // 64 bins/thread in pick

__device__ unsigned            g_hist[2][NBINS];   // [0]: fkey(v)  [1]: fkey(vo)
__device__ int                 g_base[3][NBINS];   // per-bin output offsets
__device__ unsigned            g_bin[3];           // lo0 (>=), hi1 (<=), lo2 (>=)
__device__ int                 g_nwork;
__device__ int4                g_work[WLCAP];      // {sel, bin, start, cnt}
__device__ unsigned long long  g_scat[3][CAP];
__device__ int                 g_idx[3 * KMAX];

__device__ __forceinline__ unsigned fkey(float f) {
    unsigned u = __float_as_uint(f);
    return (u & 0x80000000u) ? ~u : (u | 0x80000000u);   // monotonic
}

__device__ __forceinline__ void agg_add(unsigned* hist, unsigned bin) {
    unsigned act = __activemask();
    unsigned mm  = __match_any_sync(act, bin);
    if ((__ffs(mm) - 1) == (int)(threadIdx.x & 31))
        atomicAdd(&hist[bin], __popc(mm));
}

// ---- H: chip-wide histograms, one element per thread ------------------------
__global__ __launch_bounds__(256)
void hist_kernel(const float2* __restrict__ A2, const int* __restrict__ bag, int N) {
    const int i = blockIdx.x * 256 + threadIdx.x;
    const int bg = __ldg(bag);
    if (i >= N) return;
    float2 a = A2[i];
    float v  = bg ? a.y : a.x;
    float vo = bg ? a.x : a.y;
    agg_add(g_hist[0], fkey(v)  >> SHIFT);
    agg_add(g_hist[1], fkey(vo) >> SHIFT);
}

// ---- P: offset tables + thresholds + worklist (two-pass, no reg array) ------
// block 0: hist0 -> sel0 (top-K, suffix) + sel1 (bottom-K, prefix)
// block 1: hist1 -> sel2 (top-K, suffix)
__global__ __launch_bounds__(PICK_T)
void pick_kernel(int K) {
    const int hh  = blockIdx.x;
    const int tid = threadIdx.x;
    const unsigned* hist = g_hist[hh];
    __shared__ unsigned s[PICK_T];
    const unsigned uK = (unsigned)K;

    unsigned part = 0;
    #pragma unroll 8
    for (int j = 0; j < PBPT; j++) part += hist[tid * PBPT + j];
    s[tid] = part;
    __syncthreads();
    for (int off = 1; off < PICK_T; off <<= 1) {    // inclusive scan (ascending)
        unsigned v = (tid >= off) ? s[tid - off] : 0u;
        __syncthreads();
        s[tid] += v;
        __syncthreads();
    }
    const unsigned asc   = s[tid];
    const unsigned total = s[PICK_T - 1];

    // top-K side (sel0 from hist0, sel2 from hist1): suffix offsets
    {
        const int selt = (hh == 0) ? 0 : 2;
        unsigned acc = total - asc;                 // elems in strictly higher chunks
        for (int j = PBPT - 1; j >= 0; j--) {
            int b = tid * PBPT + j;
            unsigned c = hist[b];
            g_base[selt][b] = (int)acc;
            if (acc < uK && c > 0) {
                if (acc + c >= uK) g_bin[selt] = (unsigned)b;
                int w = atomicAdd(&g_nwork, 1);
                if (w < WLCAP) g_work[w] = make_int4(selt, b, (int)acc, (int)c);
            }
            acc += c;
        }
    }
    // bottom-K (hist0 only -> sel1): prefix offsets
    if (hh == 0) {
        unsigned acc = asc - part;                  // elems in strictly lower chunks
        for (int j = 0; j < PBPT; j++) {
            int b = tid * PBPT + j;
            unsigned c = hist[b];
            g_base[1][b] = (int)acc;
            if (acc < uK && c > 0) {
                if (acc + c >= uK) g_bin[1] = (unsigned)b;
                int w = atomicAdd(&g_nwork, 1);
                if (w < WLCAP) g_work[w] = make_int4(1, b, (int)acc, (int)c);
            }
            acc += c;
        }
    }
}

// ---- C: scatter candidates to their final segments --------------------------
__global__ __launch_bounds__(256)
void compact_kernel(const float2* __restrict__ A2, const int* __restrict__ bag, int N) {
    const int i = blockIdx.x * 256 + threadIdx.x;
    if (i >= N) return;
    const int bg = __ldg(bag);
    const unsigned lo0 = g_bin[0];
    const unsigned hi1 = g_bin[1];
    const unsigned lo2 = g_bin[2];

    float2 a = A2[i];
    float v  = bg ? a.y : a.x;
    float vo = bg ? a.x : a.y;
    unsigned k0 = fkey(v), k2 = fkey(vo);
    unsigned b0 = k0 >> SHIFT, b2 = k2 >> SHIFT;
    unsigned long long il = (unsigned)(~(unsigned)i);

    if (b0 >= lo0) {
        int p = atomicAdd(&g_base[0][b0], 1);
        if (p < CAP) g_scat[0][p] = ((unsigned long long)k0 << 32) | il;
    }
    if (b0 <= hi1) {
        int p = atomicAdd(&g_base[1][b0], 1);
        if (p < CAP) g_scat[1][p] = ((unsigned long long)(~k0) << 32) | il;
    }
    if (b2 >= lo2) {
        int p = atomicAdd(&g_base[2][b2], 1);
        if (p < CAP) g_scat[2][p] = ((unsigned long long)k2 << 32) | il;
    }
}

// ---- B: one block per segment, rank-by-comparison ----------------------------
__global__ __launch_bounds__(128)
void rank_kernel(int K) {
    __shared__ unsigned long long skeys[SEGB];
    const int tid = threadIdx.x;
    const int nwork = g_nwork < WLCAP ? g_nwork : WLCAP;

    for (int e = blockIdx.x; e < nwork; e += gridDim.x) {
        int4 w = g_work[e];
        const int sel = w.x, start = w.z;
        int cnt = w.w;
        if (start + cnt > CAP) cnt = CAP - start;
        if (cnt > SEGB) cnt = SEGB;
        if (cnt <= 0) continue;
        const unsigned long long* seg = &g_scat[sel][start];

        if (cnt == 1) {
            if (tid == 0 && start < K)
                g_idx[sel * K + start] = (int)(~(unsigned)(seg[0] & 0xFFFFFFFFull));
            continue;
        }

        for (int j = tid; j < cnt; j += 128) skeys[j] = seg[j];
        __syncthreads();

        for (int i = tid; i < cnt; i += 128) {
            unsigned long long key = skeys[i];
            int rank = 0;
            int j = 0;
            #pragma unroll 4
            for (; j + 3 < cnt; j += 4) {
                rank += (skeys[j]     > key);
                rank += (skeys[j + 1] > key);
                rank += (skeys[j + 2] > key);
                rank += (skeys[j + 3] > key);
            }
            for (; j < cnt; j++) rank += (skeys[j] > key);
            int pos = start + rank;
            if (pos < K)
                g_idx[sel * K + pos] = (int)(~(unsigned)(key & 0xFFFFFFFFull));
        }
        __syncthreads();
    }
}

// ---- G: gather + GEMV(512->2) + softmax; preamble zeroes selection state -----
__global__ __launch_bounds__(256)
void gemv_softmax_kernel(const float* __restrict__ h,
                         const float* __restrict__ W,
                         const float* __restrict__ b,
                         float* __restrict__ out,
                         int D, int K) {
    // zero state for the next graph replay (no longer needed this call)
    {
        uint4* hp = (uint4*)g_hist;
        const int totalw = 2 * NBINS / 4;
        const int per = (totalw + gridDim.x - 1) / gridDim.x;
        const int zs = blockIdx.x * per;
        const int ze = (zs + per < totalw) ? zs + per : totalw;
        for (int i = zs + threadIdx.x; i < ze; i += blockDim.x)
            hp[i] = make_uint4(0u, 0u, 0u, 0u);
        if (blockIdx.x == 0 && threadIdx.x == 0) g_nwork = 0;
    }

    extern __shared__ float ws[];   // D*2 floats, W[d*2+c]
    const int tid = threadIdx.x;
    for (int j = tid; j < D * 2; j += blockDim.x) ws[j] = W[j];
    __syncthreads();

    const int warp = tid >> 5, lane = tid & 31;
    const int rbase = (blockIdx.x * (blockDim.x >> 5) + warp) * 2;
    const int total = 3 * K;
    if (rbase >= total) return;

    const bool two = (rbase + 1 < total);
    const int ia = g_idx[rbase];
    const int ib = two ? g_idx[rbase + 1] : ia;
    const float4* pa = (const float4*)(h + (size_t)ia * D);
    const float4* pb = (const float4*)(h + (size_t)ib * D);

    float a0 = 0.f, a1 = 0.f, b0 = 0.f, b1 = 0.f;
    const int nq = D >> 2;

    int t = lane;
    for (; t + 96 < nq; t += 128) {
        float4 va0 = pa[t];
        float4 va1 = pa[t + 32];
        float4 va2 = pa[t + 64];
        float4 va3 = pa[t + 96];
        float4 vb0 = pb[t];
        float4 vb1 = pb[t + 32];
        float4 vb2 = pb[t + 64];
        float4 vb3 = pb[t + 96];
        #pragma unroll
        for (int u = 0; u < 4; u++) {
            float4 va = (u == 0) ? va0 : (u == 1) ? va1 : (u == 2) ? va2 : va3;
            float4 vb = (u == 0) ? vb0 : (u == 1) ? vb1 : (u == 2) ? vb2 : vb3;
            int j = (t + u * 32) << 3;
            a0 = fmaf(va.x, ws[j + 0], a0);  a1 = fmaf(va.x, ws[j + 1], a1);
            b0 = fmaf(vb.x, ws[j + 0], b0);  b1 = fmaf(vb.x, ws[j + 1], b1);
            a0 = fmaf(va.y, ws[j + 2], a0);  a1 = fmaf(va.y, ws[j + 3], a1);
            b0 = fmaf(vb.y, ws[j + 2], b0);  b1 = fmaf(vb.y, ws[j + 3], b1);
            a0 = fmaf(va.z, ws[j + 4], a0);  a1 = fmaf(va.z, ws[j + 5], a1);
            b0 = fmaf(vb.z, ws[j + 4], b0);  b1 = fmaf(vb.z, ws[j + 5], b1);
            a0 = fmaf(va.w, ws[j + 6], a0);  a1 = fmaf(va.w, ws[j + 7], a1);
            b0 = fmaf(vb.w, ws[j + 6], b0);  b1 = fmaf(vb.w, ws[j + 7], b1);
        }
    }
    for (; t < nq; t += 32) {
        float4 va = pa[t];
        float4 vb = pb[t];
        int j = t << 3;
        a0 = fmaf(va.x, ws[j + 0], a0);  a1 = fmaf(va.x, ws[j + 1], a1);
        b0 = fmaf(vb.x, ws[j + 0], b0);  b1 = fmaf(vb.x, ws[j + 1], b1);
        a0 = fmaf(va.y, ws[j + 2], a0);  a1 = fmaf(va.y, ws[j + 3], a1);
        b0 = fmaf(vb.y, ws[j + 2], b0);  b1 = fmaf(vb.y, ws[j + 3], b1);
        a0 = fmaf(va.z, ws[j + 4], a0);  a1 = fmaf(va.z, ws[j + 5], a1);
        b0 = fmaf(vb.z, ws[j + 4], b0);  b1 = fmaf(vb.z, ws[j + 5], b1);
        a0 = fmaf(va.w, ws[j + 6], a0);  a1 = fmaf(va.w, ws[j + 7], a1);
        b0 = fmaf(vb.w, ws[j + 6], b0);  b1 = fmaf(vb.w, ws[j + 7], b1);
    }

    #pragma unroll
    for (int o = 16; o; o >>= 1) {
        a0 += __shfl_down_sync(0xFFFFFFFFu, a0, o);
        a1 += __shfl_down_sync(0xFFFFFFFFu, a1, o);
        b0 += __shfl_down_sync(0xFFFFFFFFu, b0, o);
        b1 += __shfl_down_sync(0xFFFFFFFFu, b1, o);
    }

    if (lane == 0) {
        float bb0 = b[0], bb1 = b[1];
        {
            int r = rbase;
            float z0 = a0 + bb0, z1 = a1 + bb1;
            float m = fmaxf(z0, z1);
            float e0 = expf(z0 - m), e1 = expf(z1 - m);
            float inv = 1.0f / (e0 + e1);
            out[r] = (r < K) ? 1.0f : 0.0f;
            out[3 * K + r * 2 + 0] = z0;
            out[3 * K + r * 2 + 1] = z1;
            out[9 * K + r * 2 + 0] = e0 * inv;
            out[9 * K + r * 2 + 1] = e1 * inv;
        }
        if (two) {
            int r = rbase + 1;
            float z0 = b0 + bb0, z1 = b1 + bb1;
            float m = fmaxf(z0, z1);
            float e0 = expf(z0 - m), e1 = expf(z1 - m);
            float inv = 1.0f / (e0 + e1);
            out[r] = (r < K) ? 1.0f : 0.0f;
            out[3 * K + r * 2 + 0] = z0;
            out[3 * K + r * 2 + 1] = z1;
            out[9 * K + r * 2 + 0] = e0 * inv;
            out[9 * K + r * 2 + 1] = e1 * inv;
        }
    }
}

extern "C" void kernel_launch(void* const* d_in, const int* in_sizes, int n_in,
                              void* d_out, int out_size) {
    const float* h = (const float*)d_in[0];   // (N,1,D)
    const float* A = (const float*)d_in[1];   // (N,1,2)
    const float* W = (const float*)d_in[2];   // (D,2)
    const float* b = (const float*)d_in[3];   // (2,)
    const int* bag = (const int*)d_in[4];

    const int N = in_sizes[1] / 2;
    const int D = in_sizes[0] / N;
    int K = (int)(0.02 * (double)N);
    if (K == 0) K = 8;
    if (K > KMAX) K = KMAX;

    const float2* A2 = (const float2*)A;
    const int grid = (N + 255) / 256;

    hist_kernel<<<grid, 256>>>(A2, bag, N);
    pick_kernel<<<2, PICK_T>>>(K);
    compact_kernel<<<grid, 256>>>(A2, bag, N);
    rank_kernel<<<1024, 128>>>(K);

    const int rows = 3 * K;
    const int blocks = (rows + 15) / 16;      // 8 warps x 2 rows per block
    const size_t smem = (size_t)(D * 2) * sizeof(float);
    gemv_softmax_kernel<<<blocks, 256, smem>>>(h, W, b, (float*)d_out, D, K);
}

// round 8
// speedup vs baseline: 3.9800x; 3.9800x over previous
#include <cuda_runtime.h>
#include <cuda_bf16.h>
#include <math.h>

// ---------------------------------------------------------------------------
// 3x exact top-K over columns of A (N x 2), (value desc, index asc) = lax.top_k.
// 4-launch pipeline:
//   HP: chip-wide 16384-bin histograms of fkey(v), fkey(vo); LAST block (via
//       done-counter + single release/acquire fence) builds per-bin offset
//       tables g_base, threshold bins g_bin, worklist of segments
//   C:  scatter candidates to their final SEGMENT via atomicAdd(g_base)
//   R:  one block per worklist segment: rank-by-comparison (keys unique),
//       write g_idx[start + rank] directly
//   G:  gather h rows, 512->2 GEMV (conflict-free smem W), softmax(2);
//       preamble zeroes g_hist/g_nwork for the next graph replay
// State zero at module load; every call ends with state re-zeroed => each call
// (correctness run and every graph replay) sees identical initial state.
// Output (float32, 15K): [0,3K) labels | [3K,9K) logits | [9K,15K) softmax
// ---------------------------------------------------------------------------

#define NBINS   16384
#define SHIFT   18
#define CAP     4096
#define KMAX    2048
#define SEGB    1024              // max keys ranked per segment (smem 8KB)
#define WLCAP   8192
#define HP_T    1024
#define PBPT    (NBINS / HP_T)    // 16 bins/thread in pick

__device__ unsigned            g_hist[2][NBINS];   // [0]: fkey(v)  [1]: fkey(vo)
__device__ unsigned            g_done;
__device__ int                 g_base[3][NBINS];   // per-bin output offsets
__device__ unsigned            g_bin[3];           // lo0 (>=), hi1 (<=), lo2 (>=)
__device__ int                 g_nwork;
__device__ int4                g_work[WLCAP];      // {sel, bin, start, cnt}
__device__ unsigned long long  g_scat[3][CAP];
__device__ int                 g_idx[3 * KMAX];

__device__ __forceinline__ unsigned fkey(float f) {
    unsigned u = __float_as_uint(f);
    return (u & 0x80000000u) ? ~u : (u | 0x80000000u);   // monotonic
}

// ---- HP: histograms + fused pick in last block -------------------------------
__global__ __launch_bounds__(HP_T)
void hist_pick_kernel(const float2* __restrict__ A2, const int* __restrict__ bag,
                      int N, int K) {
    const int tid = threadIdx.x;
    const int i = blockIdx.x * HP_T + tid;
    const int bg = __ldg(bag);

    if (i < N) {
        float2 a = A2[i];
        float v  = bg ? a.y : a.x;
        float vo = bg ? a.x : a.y;
        atomicAdd(&g_hist[0][fkey(v)  >> SHIFT], 1u);
        atomicAdd(&g_hist[1][fkey(vo) >> SHIFT], 1u);
    }
    __syncthreads();

    __shared__ bool amLast;
    if (tid == 0) {
        __threadfence();                       // release: block's atomics -> done
        unsigned prev = atomicAdd(&g_done, 1u);
        amLast = (prev == (unsigned)gridDim.x - 1u);
        if (amLast) __threadfence();           // acquire side
    }
    __syncthreads();
    if (!amLast) return;
    if (tid == 0) g_done = 0u;                 // reset for next replay

    __shared__ unsigned s[HP_T];
    const unsigned uK = (unsigned)K;

    #pragma unroll
    for (int hh = 0; hh < 2; hh++) {
        const uint4* h4 = (const uint4*)g_hist[hh];
        unsigned cnt[PBPT];
        #pragma unroll
        for (int q = 0; q < PBPT / 4; q++) {
            uint4 c = __ldcg(&h4[tid * (PBPT / 4) + q]);
            cnt[q * 4 + 0] = c.x; cnt[q * 4 + 1] = c.y;
            cnt[q * 4 + 2] = c.z; cnt[q * 4 + 3] = c.w;
        }
        unsigned part = 0;
        #pragma unroll
        for (int j = 0; j < PBPT; j++) part += cnt[j];
        s[tid] = part;
        __syncthreads();
        for (int off = 1; off < HP_T; off <<= 1) {     // inclusive scan
            unsigned v = (tid >= off) ? s[tid - off] : 0u;
            __syncthreads();
            s[tid] += v;
            __syncthreads();
        }
        const unsigned asc   = s[tid];
        const unsigned total = s[HP_T - 1];

        int basev[PBPT];
        // top-K (sel0 from hist0, sel2 from hist1): suffix offsets
        {
            const int selt = (hh == 0) ? 0 : 2;
            unsigned acc = total - asc;                // strictly-higher chunks
            #pragma unroll
            for (int j = PBPT - 1; j >= 0; j--) {
                int b = tid * PBPT + j;
                basev[j] = (int)acc;
                if (acc < uK && cnt[j] > 0) {
                    if (acc + cnt[j] >= uK) g_bin[selt] = (unsigned)b;
                    int w = atomicAdd(&g_nwork, 1);
                    if (w < WLCAP) g_work[w] = make_int4(selt, b, (int)acc, (int)cnt[j]);
                }
                acc += cnt[j];
            }
            int4* gb4 = (int4*)g_base[selt];
            #pragma unroll
            for (int q = 0; q < PBPT / 4; q++)
                gb4[tid * (PBPT / 4) + q] = make_int4(basev[q * 4 + 0], basev[q * 4 + 1],
                                                      basev[q * 4 + 2], basev[q * 4 + 3]);
        }
        // bottom-K (hist0 only -> sel1): prefix offsets
        if (hh == 0) {
            unsigned acc = asc - part;                 // strictly-lower chunks
            #pragma unroll
            for (int j = 0; j < PBPT; j++) {
                int b = tid * PBPT + j;
                basev[j] = (int)acc;
                if (acc < uK && cnt[j] > 0) {
                    if (acc + cnt[j] >= uK) g_bin[1] = (unsigned)b;
                    int w = atomicAdd(&g_nwork, 1);
                    if (w < WLCAP) g_work[w] = make_int4(1, b, (int)acc, (int)cnt[j]);
                }
                acc += cnt[j];
            }
            int4* gb4 = (int4*)g_base[1];
            #pragma unroll
            for (int q = 0; q < PBPT / 4; q++)
                gb4[tid * (PBPT / 4) + q] = make_int4(basev[q * 4 + 0], basev[q * 4 + 1],
                                                      basev[q * 4 + 2], basev[q * 4 + 3]);
        }
        __syncthreads();
    }
}

// ---- C: scatter candidates to their final segments --------------------------
__global__ __launch_bounds__(256)
void compact_kernel(const float2* __restrict__ A2, const int* __restrict__ bag, int N) {
    const int i = blockIdx.x * 256 + threadIdx.x;
    if (i >= N) return;
    const int bg = __ldg(bag);
    const unsigned lo0 = g_bin[0];
    const unsigned hi1 = g_bin[1];
    const unsigned lo2 = g_bin[2];

    float2 a = A2[i];
    float v  = bg ? a.y : a.x;
    float vo = bg ? a.x : a.y;
    unsigned k0 = fkey(v), k2 = fkey(vo);
    unsigned b0 = k0 >> SHIFT, b2 = k2 >> SHIFT;
    unsigned long long il = (unsigned)(~(unsigned)i);

    if (b0 >= lo0) {
        int p = atomicAdd(&g_base[0][b0], 1);
        if (p < CAP) g_scat[0][p] = ((unsigned long long)k0 << 32) | il;
    }
    if (b0 <= hi1) {
        int p = atomicAdd(&g_base[1][b0], 1);
        if (p < CAP) g_scat[1][p] = ((unsigned long long)(~k0) << 32) | il;
    }
    if (b2 >= lo2) {
        int p = atomicAdd(&g_base[2][b2], 1);
        if (p < CAP) g_scat[2][p] = ((unsigned long long)k2 << 32) | il;
    }
}

// ---- R: one block per segment, rank-by-comparison ----------------------------
__global__ __launch_bounds__(128)
void rank_kernel(int K) {
    __shared__ unsigned long long skeys[SEGB];
    const int tid = threadIdx.x;
    const int nwork = g_nwork < WLCAP ? g_nwork : WLCAP;

    for (int e = blockIdx.x; e < nwork; e += gridDim.x) {
        int4 w = g_work[e];
        const int sel = w.x, start = w.z;
        int cnt = w.w;
        if (start + cnt > CAP) cnt = CAP - start;
        if (cnt > SEGB) cnt = SEGB;
        if (cnt <= 0) continue;
        const unsigned long long* seg = &g_scat[sel][start];

        if (cnt == 1) {
            if (tid == 0 && start < K)
                g_idx[sel * K + start] = (int)(~(unsigned)(seg[0] & 0xFFFFFFFFull));
            continue;
        }

        for (int j = tid; j < cnt; j += 128) skeys[j] = seg[j];
        __syncthreads();

        for (int i = tid; i < cnt; i += 128) {
            unsigned long long key = skeys[i];
            int rank = 0;
            int j = 0;
            #pragma unroll 4
            for (; j + 3 < cnt; j += 4) {
                rank += (skeys[j]     > key);
                rank += (skeys[j + 1] > key);
                rank += (skeys[j + 2] > key);
                rank += (skeys[j + 3] > key);
            }
            for (; j < cnt; j++) rank += (skeys[j] > key);
            int pos = start + rank;
            if (pos < K)
                g_idx[sel * K + pos] = (int)(~(unsigned)(key & 0xFFFFFFFFull));
        }
        __syncthreads();
    }
}

// ---- G: gather + GEMV(512->2) + softmax; conflict-free W; zero preamble ------
__global__ __launch_bounds__(256)
void gemv_softmax_kernel(const float* __restrict__ h,
                         const float* __restrict__ W,
                         const float* __restrict__ b,
                         float* __restrict__ out,
                         int D, int K) {
    // zero selection state for the next graph replay
    {
        uint4* hp = (uint4*)g_hist;
        const int totalw = 2 * NBINS / 4;
        const int per = (totalw + gridDim.x - 1) / gridDim.x;
        const int zs = blockIdx.x * per;
        const int ze = (zs + per < totalw) ? zs + per : totalw;
        for (int i = zs + threadIdx.x; i < ze; i += blockDim.x)
            hp[i] = make_uint4(0u, 0u, 0u, 0u);
        if (blockIdx.x == 0 && threadIdx.x == 0) g_nwork = 0;
    }

    extern __shared__ float ws[];          // [0,D): W[:,0]   [D,2D): W[:,1]
    float* ws0 = ws;
    float* ws1 = ws + D;
    const int tid = threadIdx.x;
    for (int j = tid; j < D; j += blockDim.x) {
        ws0[j] = W[j * 2 + 0];
        ws1[j] = W[j * 2 + 1];
    }
    __syncthreads();

    const float4* w04 = (const float4*)ws0;
    const float4* w14 = (const float4*)ws1;

    const int warp = tid >> 5, lane = tid & 31;
    const int rbase = (blockIdx.x * (blockDim.x >> 5) + warp) * 2;
    const int total = 3 * K;
    if (rbase >= total) return;

    const bool two = (rbase + 1 < total);
    const int ia = g_idx[rbase];
    const int ib = two ? g_idx[rbase + 1] : ia;
    const float4* pa = (const float4*)(h + (size_t)ia * D);
    const float4* pb = (const float4*)(h + (size_t)ib * D);

    float a0 = 0.f, a1 = 0.f, b0 = 0.f, b1 = 0.f;
    const int nq = D >> 2;

    int t = lane;
    for (; t + 96 < nq; t += 128) {
        float4 va0 = pa[t];
        float4 va1 = pa[t + 32];
        float4 va2 = pa[t + 64];
        float4 va3 = pa[t + 96];
        float4 vb0 = pb[t];
        float4 vb1 = pb[t + 32];
        float4 vb2 = pb[t + 64];
        float4 vb3 = pb[t + 96];
        #pragma unroll
        for (int u = 0; u < 4; u++) {
            float4 va = (u == 0) ? va0 : (u == 1) ? va1 : (u == 2) ? va2 : va3;
            float4 vb = (u == 0) ? vb0 : (u == 1) ? vb1 : (u == 2) ? vb2 : vb3;
            float4 w0 = w04[t + u * 32];   // conflict-free: lane-contiguous 16B
            float4 w1 = w14[t + u * 32];
            a0 = fmaf(va.x, w0.x, a0);  a1 = fmaf(va.x, w1.x, a1);
            b0 = fmaf(vb.x, w0.x, b0);  b1 = fmaf(vb.x, w1.x, b1);
            a0 = fmaf(va.y, w0.y, a0);  a1 = fmaf(va.y, w1.y, a1);
            b0 = fmaf(vb.y, w0.y, b0);  b1 = fmaf(vb.y, w1.y, b1);
            a0 = fmaf(va.z, w0.z, a0);  a1 = fmaf(va.z, w1.z, a1);
            b0 = fmaf(vb.z, w0.z, b0);  b1 = fmaf(vb.z, w1.z, b1);
            a0 = fmaf(va.w, w0.w, a0);  a1 = fmaf(va.w, w1.w, a1);
            b0 = fmaf(vb.w, w0.w, b0);  b1 = fmaf(vb.w, w1.w, b1);
        }
    }
    for (; t < nq; t += 32) {
        float4 va = pa[t];
        float4 vb = pb[t];
        float4 w0 = w04[t];
        float4 w1 = w14[t];
        a0 = fmaf(va.x, w0.x, a0);  a1 = fmaf(va.x, w1.x, a1);
        b0 = fmaf(vb.x, w0.x, b0);  b1 = fmaf(vb.x, w1.x, b1);
        a0 = fmaf(va.y, w0.y, a0);  a1 = fmaf(va.y, w1.y, a1);
        b0 = fmaf(vb.y, w0.y, b0);  b1 = fmaf(vb.y, w1.y, b1);
        a0 = fmaf(va.z, w0.z, a0);  a1 = fmaf(va.z, w1.z, a1);
        b0 = fmaf(vb.z, w0.z, b0);  b1 = fmaf(vb.z, w1.z, b1);
        a0 = fmaf(va.w, w0.w, a0);  a1 = fmaf(va.w, w1.w, a1);
        b0 = fmaf(vb.w, w0.w, b0);  b1 = fmaf(vb.w, w1.w, b1);
    }

    #pragma unroll
    for (int o = 16; o; o >>= 1) {
        a0 += __shfl_down_sync(0xFFFFFFFFu, a0, o);
        a1 += __shfl_down_sync(0xFFFFFFFFu, a1, o);
        b0 += __shfl_down_sync(0xFFFFFFFFu, b0, o);
        b1 += __shfl_down_sync(0xFFFFFFFFu, b1, o);
    }

    if (lane == 0) {
        float bb0 = b[0], bb1 = b[1];
        {
            int r = rbase;
            float z0 = a0 + bb0, z1 = a1 + bb1;
            float m = fmaxf(z0, z1);
            float e0 = expf(z0 - m), e1 = expf(z1 - m);
            float inv = 1.0f / (e0 + e1);
            out[r] = (r < K) ? 1.0f : 0.0f;
            out[3 * K + r * 2 + 0] = z0;
            out[3 * K + r * 2 + 1] = z1;
            out[9 * K + r * 2 + 0] = e0 * inv;
            out[9 * K + r * 2 + 1] = e1 * inv;
        }
        if (two) {
            int r = rbase + 1;
            float z0 = b0 + bb0, z1 = b1 + bb1;
            float m = fmaxf(z0, z1);
            float e0 = expf(z0 - m), e1 = expf(z1 - m);
            float inv = 1.0f / (e0 + e1);
            out[r] = (r < K) ? 1.0f : 0.0f;
            out[3 * K + r * 2 + 0] = z0;
            out[3 * K + r * 2 + 1] = z1;
            out[9 * K + r * 2 + 0] = e0 * inv;
            out[9 * K + r * 2 + 1] = e1 * inv;
        }
    }
}

extern "C" void kernel_launch(void* const* d_in, const int* in_sizes, int n_in,
                              void* d_out, int out_size) {
    const float* h = (const float*)d_in[0];   // (N,1,D)
    const float* A = (const float*)d_in[1];   // (N,1,2)
    const float* W = (const float*)d_in[2];   // (D,2)
    const float* b = (const float*)d_in[3];   // (2,)
    const int* bag = (const int*)d_in[4];

    const int N = in_sizes[1] / 2;
    const int D = in_sizes[0] / N;
    int K = (int)(0.02 * (double)N);
    if (K == 0) K = 8;
    if (K > KMAX) K = KMAX;

    const float2* A2 = (const float2*)A;

    hist_pick_kernel<<<(N + HP_T - 1) / HP_T, HP_T>>>(A2, bag, N, K);
    compact_kernel<<<(N + 255) / 256, 256>>>(A2, bag, N);
    rank_kernel<<<512, 128>>>(K);

    const int rows = 3 * K;
    const int blocks = (rows + 15) / 16;      // 8 warps x 2 rows per block
    const size_t smem = (size_t)(D * 2) * sizeof(float);
    gemv_softmax_kernel<<<blocks, 256, smem>>>(h, W, b, (float*)d_out, D, K);
}

// round 9
// speedup vs baseline: 5.2687x; 1.3238x over previous
#include <cuda_runtime.h>
#include <cuda_bf16.h>
#include <math.h>

// ---------------------------------------------------------------------------
// SINGLE-KERNEL fused pipeline (persistent grid + device grid barriers).
// 3x exact top-K over columns of A (N x 2), (value desc, index asc) = lax.top_k.
// Phases (separated by generation-counter grid barriers, 296 co-resident blocks):
//   1 hist     : 16384-bin histograms of fkey(v), fkey(vo)
//   2 bsum     : per-64-bin-chunk sums (256 chunks, warp reductions)
//   3 scan     : block 0 scans the 256 chunk sums per hist
//   4 base     : per-chunk offset tables g_base, thresholds g_bin, worklist
//   5 compact  : scatter candidates to final segment via atomicAdd(g_base)
//   6 rank     : one block per segment, rank-by-comparison (keys unique)
//   7 gemv     : gather h rows, 512->2 GEMV (smem W), softmax(2); zero state
// State zero at module load; phase 7 re-zeroes => every call identical.
// Output (float32, 15K): [0,3K) labels | [3K,9K) logits | [9K,15K) softmax
// ---------------------------------------------------------------------------

#define NBINS   16384
#define SHIFT   18
#define NCHUNK  256
#define CH      (NBINS / NCHUNK)   // 64 bins per chunk
#define CAP     4096
#define KMAX    2048
#define SEGB    1024
#define WLCAP   8192
#define BLKS    296
#define THR     256

__device__ unsigned            g_hist[2][NBINS];
__device__ unsigned            g_bsum[2][NCHUNK];
__device__ unsigned            g_boff[2][NCHUNK];   // exclusive chunk offsets
__device__ unsigned            g_btot[2];
__device__ int                 g_base[3][NBINS];
__device__ unsigned            g_bin[3];            // lo0 (>=), hi1 (<=), lo2 (>=)
__device__ int                 g_nwork;
__device__ int4                g_work[WLCAP];       // {sel, bin, start, cnt}
__device__ unsigned long long  g_scat[3][CAP];
__device__ int                 g_idx[3 * KMAX];
__device__ unsigned            g_arrive;
__device__ volatile unsigned   g_gen;

__device__ __forceinline__ unsigned fkey(float f) {
    unsigned u = __float_as_uint(f);
    return (u & 0x80000000u) ? ~u : (u | 0x80000000u);   // monotonic
}

// Generation-counter grid barrier. Safe: all BLKS blocks are co-resident
// (__launch_bounds__(THR,2) -> >=304 resident blocks on 152 SMs).
__device__ __forceinline__ void grid_sync() {
    __syncthreads();
    if (threadIdx.x == 0) {
        unsigned gen = g_gen;
        __threadfence();                               // release my block's writes
        if (atomicAdd(&g_arrive, 1u) == (unsigned)BLKS - 1u) {
            g_arrive = 0u;
            __threadfence();
            g_gen = gen + 1u;
        } else {
            while (g_gen == gen) __nanosleep(64);
            __threadfence();                           // acquire others' writes
        }
    }
    __syncthreads();
}

__global__ __launch_bounds__(THR, 2)
void fused_kernel(const float* __restrict__ h, const float2* __restrict__ A2,
                  const float* __restrict__ W, const float* __restrict__ bvec,
                  const int* __restrict__ bag, float* __restrict__ out,
                  int N, int D, int K) {
    __shared__ unsigned long long s_u64[SEGB];        // 8KB, aliased per phase
    unsigned* s_u32 = (unsigned*)s_u64;
    float*    s_f   = (float*)s_u64;

    const int tid = threadIdx.x;
    const int bid = blockIdx.x;
    const int bg  = __ldg(bag);
    const unsigned uK = (unsigned)K;

    // ---- phase 1: histograms -------------------------------------------------
    for (int i = bid * THR + tid; i < N; i += BLKS * THR) {
        float2 a = A2[i];
        float v  = bg ? a.y : a.x;
        float vo = bg ? a.x : a.y;
        atomicAdd(&g_hist[0][fkey(v)  >> SHIFT], 1u);
        atomicAdd(&g_hist[1][fkey(vo) >> SHIFT], 1u);
    }
    grid_sync();

    // ---- phase 2: per-chunk sums (blocks < NCHUNK; warp hh handles hist hh) ---
    if (bid < NCHUNK) {
        const int warp = tid >> 5, lane = tid & 31;
        if (warp < 2) {
            unsigned ss = g_hist[warp][bid * CH + lane] +
                          g_hist[warp][bid * CH + lane + 32];
            #pragma unroll
            for (int o = 16; o; o >>= 1) ss += __shfl_down_sync(0xFFFFFFFFu, ss, o);
            if (lane == 0) g_bsum[warp][bid] = ss;
        }
    }
    grid_sync();

    // ---- phase 3: block 0 scans the NCHUNK chunk sums per hist ----------------
    if (bid == 0) {
        #pragma unroll
        for (int hh = 0; hh < 2; hh++) {
            unsigned v = g_bsum[hh][tid];             // THR == NCHUNK
            s_u32[tid] = v;
            __syncthreads();
            for (int off = 1; off < NCHUNK; off <<= 1) {
                unsigned w = (tid >= off) ? s_u32[tid - off] : 0u;
                __syncthreads();
                s_u32[tid] += w;
                __syncthreads();
            }
            unsigned incl = s_u32[tid];
            g_boff[hh][tid] = incl - v;
            if (tid == NCHUNK - 1) g_btot[hh] = incl;
            __syncthreads();
        }
    }
    grid_sync();

    // ---- phase 4: offset tables + thresholds + worklist (blocks < NCHUNK) -----
    if (bid < NCHUNK) {
        #pragma unroll
        for (int hh = 0; hh < 2; hh++) {
            unsigned cnt = 0;
            if (tid < CH) { cnt = g_hist[hh][bid * CH + tid]; s_u32[tid] = cnt; }
            __syncthreads();
            for (int off = 1; off < CH; off <<= 1) {
                unsigned w = (tid < CH && tid >= off) ? s_u32[tid - off] : 0u;
                __syncthreads();
                if (tid < CH) s_u32[tid] += w;
                __syncthreads();
            }
            if (tid < CH) {
                const int b = bid * CH + tid;
                const unsigned incl  = s_u32[tid] + g_boff[hh][bid];
                const unsigned total = g_btot[hh];
                // top-K (sel0 from hist0, sel2 from hist1)
                const int selt = hh ? 2 : 0;
                const unsigned above = total - incl;
                g_base[selt][b] = (int)above;
                if (above < uK && cnt > 0) {
                    if (above + cnt >= uK) g_bin[selt] = (unsigned)b;
                    int w = atomicAdd(&g_nwork, 1);
                    if (w < WLCAP) g_work[w] = make_int4(selt, b, (int)above, (int)cnt);
                }
                // bottom-K (hist0 -> sel1)
                if (hh == 0) {
                    const unsigned below = incl - cnt;
                    g_base[1][b] = (int)below;
                    if (below < uK && cnt > 0) {
                        if (below + cnt >= uK) g_bin[1] = (unsigned)b;
                        int w = atomicAdd(&g_nwork, 1);
                        if (w < WLCAP) g_work[w] = make_int4(1, b, (int)below, (int)cnt);
                    }
                }
            }
            __syncthreads();
        }
    }
    grid_sync();

    // ---- phase 5: compact/scatter ---------------------------------------------
    {
        const unsigned lo0 = g_bin[0], hi1 = g_bin[1], lo2 = g_bin[2];
        for (int i = bid * THR + tid; i < N; i += BLKS * THR) {
            float2 a = A2[i];
            float v  = bg ? a.y : a.x;
            float vo = bg ? a.x : a.y;
            unsigned k0 = fkey(v), k2 = fkey(vo);
            unsigned b0 = k0 >> SHIFT, b2 = k2 >> SHIFT;
            unsigned long long il = (unsigned)(~(unsigned)i);
            if (b0 >= lo0) {
                int p = atomicAdd(&g_base[0][b0], 1);
                if (p < CAP) g_scat[0][p] = ((unsigned long long)k0 << 32) | il;
            }
            if (b0 <= hi1) {
                int p = atomicAdd(&g_base[1][b0], 1);
                if (p < CAP) g_scat[1][p] = ((unsigned long long)(~k0) << 32) | il;
            }
            if (b2 >= lo2) {
                int p = atomicAdd(&g_base[2][b2], 1);
                if (p < CAP) g_scat[2][p] = ((unsigned long long)k2 << 32) | il;
            }
        }
    }
    grid_sync();

    // ---- phase 6: rank segments -------------------------------------------------
    {
        const int nwork = g_nwork < WLCAP ? g_nwork : WLCAP;
        for (int e = bid; e < nwork; e += BLKS) {
            int4 w = g_work[e];
            const int sel = w.x, start = w.z;
            int cnt = w.w;
            if (start + cnt > CAP) cnt = CAP - start;
            if (cnt > SEGB) cnt = SEGB;
            if (cnt <= 0) continue;
            const unsigned long long* seg = &g_scat[sel][start];

            if (cnt == 1) {
                if (tid == 0 && start < K)
                    g_idx[sel * K + start] = (int)(~(unsigned)(seg[0] & 0xFFFFFFFFull));
                continue;
            }
            for (int j = tid; j < cnt; j += THR) s_u64[j] = seg[j];
            __syncthreads();
            for (int i = tid; i < cnt; i += THR) {
                unsigned long long key = s_u64[i];
                int rank = 0;
                int j = 0;
                #pragma unroll 4
                for (; j + 3 < cnt; j += 4) {
                    rank += (s_u64[j]     > key);
                    rank += (s_u64[j + 1] > key);
                    rank += (s_u64[j + 2] > key);
                    rank += (s_u64[j + 3] > key);
                }
                for (; j < cnt; j++) rank += (s_u64[j] > key);
                int pos = start + rank;
                if (pos < K)
                    g_idx[sel * K + pos] = (int)(~(unsigned)(key & 0xFFFFFFFFull));
            }
            __syncthreads();
        }
    }
    grid_sync();

    // ---- phase 7: zero state + gemv/softmax --------------------------------------
    {
        // zero selection state for the next graph replay
        uint4* hp = (uint4*)g_hist;
        const int totalw = 2 * NBINS / 4;
        for (int i = bid * THR + tid; i < totalw; i += BLKS * THR)
            hp[i] = make_uint4(0u, 0u, 0u, 0u);
        if (bid == 0 && tid == 0) g_nwork = 0;

        float* ws0 = s_f;            // [0,D): W[:,0]
        float* ws1 = s_f + D;        // [D,2D): W[:,1]
        for (int j = tid; j < D; j += THR) {
            ws0[j] = W[j * 2 + 0];
            ws1[j] = W[j * 2 + 1];
        }
        __syncthreads();
        const float4* w04 = (const float4*)ws0;
        const float4* w14 = (const float4*)ws1;

        const int warp = tid >> 5, lane = tid & 31;
        const int nwarps = BLKS * (THR >> 5);
        const int wgid = bid * (THR >> 5) + warp;
        const int total = 3 * K;
        const int nq = D >> 2;
        const float bb0 = bvec[0], bb1 = bvec[1];

        for (int rbase = wgid * 2; rbase < total; rbase += nwarps * 2) {
            const bool two = (rbase + 1 < total);
            const int ia = g_idx[rbase];
            const int ib = two ? g_idx[rbase + 1] : ia;
            const float4* pa = (const float4*)(h + (size_t)ia * D);
            const float4* pb = (const float4*)(h + (size_t)ib * D);

            float a0 = 0.f, a1 = 0.f, b0 = 0.f, b1 = 0.f;
            int t = lane;
            for (; t + 96 < nq; t += 128) {
                float4 va0 = pa[t];
                float4 va1 = pa[t + 32];
                float4 va2 = pa[t + 64];
                float4 va3 = pa[t + 96];
                float4 vb0 = pb[t];
                float4 vb1 = pb[t + 32];
                float4 vb2 = pb[t + 64];
                float4 vb3 = pb[t + 96];
                #pragma unroll
                for (int u = 0; u < 4; u++) {
                    float4 va = (u == 0) ? va0 : (u == 1) ? va1 : (u == 2) ? va2 : va3;
                    float4 vb = (u == 0) ? vb0 : (u == 1) ? vb1 : (u == 2) ? vb2 : vb3;
                    float4 w0 = w04[t + u * 32];
                    float4 w1 = w14[t + u * 32];
                    a0 = fmaf(va.x, w0.x, a0);  a1 = fmaf(va.x, w1.x, a1);
                    b0 = fmaf(vb.x, w0.x, b0);  b1 = fmaf(vb.x, w1.x, b1);
                    a0 = fmaf(va.y, w0.y, a0);  a1 = fmaf(va.y, w1.y, a1);
                    b0 = fmaf(vb.y, w0.y, b0);  b1 = fmaf(vb.y, w1.y, b1);
                    a0 = fmaf(va.z, w0.z, a0);  a1 = fmaf(va.z, w1.z, a1);
                    b0 = fmaf(vb.z, w0.z, b0);  b1 = fmaf(vb.z, w1.z, b1);
                    a0 = fmaf(va.w, w0.w, a0);  a1 = fmaf(va.w, w1.w, a1);
                    b0 = fmaf(vb.w, w0.w, b0);  b1 = fmaf(vb.w, w1.w, b1);
                }
            }
            for (; t < nq; t += 32) {
                float4 va = pa[t];
                float4 vb = pb[t];
                float4 w0 = w04[t];
                float4 w1 = w14[t];
                a0 = fmaf(va.x, w0.x, a0);  a1 = fmaf(va.x, w1.x, a1);
                b0 = fmaf(vb.x, w0.x, b0);  b1 = fmaf(vb.x, w1.x, b1);
                a0 = fmaf(va.y, w0.y, a0);  a1 = fmaf(va.y, w1.y, a1);
                b0 = fmaf(vb.y, w0.y, b0);  b1 = fmaf(vb.y, w1.y, b1);
                a0 = fmaf(va.z, w0.z, a0);  a1 = fmaf(va.z, w1.z, a1);
                b0 = fmaf(vb.z, w0.z, b0);  b1 = fmaf(vb.z, w1.z, b1);
                a0 = fmaf(va.w, w0.w, a0);  a1 = fmaf(va.w, w1.w, a1);
                b0 = fmaf(vb.w, w0.w, b0);  b1 = fmaf(vb.w, w1.w, b1);
            }
            #pragma unroll
            for (int o = 16; o; o >>= 1) {
                a0 += __shfl_down_sync(0xFFFFFFFFu, a0, o);
                a1 += __shfl_down_sync(0xFFFFFFFFu, a1, o);
                b0 += __shfl_down_sync(0xFFFFFFFFu, b0, o);
                b1 += __shfl_down_sync(0xFFFFFFFFu, b1, o);
            }
            if (lane == 0) {
                {
                    int r = rbase;
                    float z0 = a0 + bb0, z1 = a1 + bb1;
                    float m = fmaxf(z0, z1);
                    float e0 = expf(z0 - m), e1 = expf(z1 - m);
                    float inv = 1.0f / (e0 + e1);
                    out[r] = (r < K) ? 1.0f : 0.0f;
                    out[3 * K + r * 2 + 0] = z0;
                    out[3 * K + r * 2 + 1] = z1;
                    out[9 * K + r * 2 + 0] = e0 * inv;
                    out[9 * K + r * 2 + 1] = e1 * inv;
                }
                if (two) {
                    int r = rbase + 1;
                    float z0 = b0 + bb0, z1 = b1 + bb1;
                    float m = fmaxf(z0, z1);
                    float e0 = expf(z0 - m), e1 = expf(z1 - m);
                    float inv = 1.0f / (e0 + e1);
                    out[r] = (r < K) ? 1.0f : 0.0f;
                    out[3 * K + r * 2 + 0] = z0;
                    out[3 * K + r * 2 + 1] = z1;
                    out[9 * K + r * 2 + 0] = e0 * inv;
                    out[9 * K + r * 2 + 1] = e1 * inv;
                }
            }
        }
    }
}

extern "C" void kernel_launch(void* const* d_in, const int* in_sizes, int n_in,
                              void* d_out, int out_size) {
    const float* h = (const float*)d_in[0];   // (N,1,D)
    const float* A = (const float*)d_in[1];   // (N,1,2)
    const float* W = (const float*)d_in[2];   // (D,2)
    const float* b = (const float*)d_in[3];   // (2,)
    const int* bag = (const int*)d_in[4];

    const int N = in_sizes[1] / 2;
    const int D = in_sizes[0] / N;
    int K = (int)(0.02 * (double)N);
    if (K == 0) K = 8;
    if (K > KMAX) K = KMAX;

    fused_kernel<<<BLKS, THR>>>(h, (const float2*)A, W, b, bag,
                                (float*)d_out, N, D, K);
}

// round 10
// speedup vs baseline: 5.5556x; 1.0545x over previous
#include <cuda_runtime.h>
#include <cuda_bf16.h>
#include <math.h>

// ---------------------------------------------------------------------------
// SINGLE-KERNEL fused pipeline (persistent grid + device grid barriers).
// 3x exact top-K over columns of A (N x 2), (value desc, index asc) = lax.top_k.
// Phases (5 generation-counter grid barriers, 296 co-resident blocks):
//   1 hist     : 16384-bin histograms of fkey(v), fkey(vo)  (float4, 2 elem/thr)
//   2 bsum     : per-64-bin-chunk sums (256 chunks, warp reductions)
//   3 base     : EVERY chunk-block redundantly scans the 256 chunk sums in smem,
//                then builds its chunk's offset table, thresholds, worklist
//   4 compact  : scatter candidates to final segment via atomicAdd(g_base)
//   5 rank     : one block per segment, rank-by-comparison (keys unique)
//   6 gemv     : 4 rows/warp gather + 512->2 GEMV (smem W) + softmax; zero state
// State zero at module load; last phase re-zeroes => every call identical.
// Output (float32, 15K): [0,3K) labels | [3K,9K) logits | [9K,15K) softmax
// ---------------------------------------------------------------------------

#define NBINS   16384
#define SHIFT   18
#define NCHUNK  256
#define CH      (NBINS / NCHUNK)   // 64 bins per chunk
#define CAP     4096
#define KMAX    2048
#define SEGB    1024
#define WLCAP   8192
#define BLKS    296
#define THR     256

__device__ unsigned            g_hist[2][NBINS];
__device__ unsigned            g_bsum[2][NCHUNK];
__device__ int                 g_base[3][NBINS];
__device__ unsigned            g_bin[3];            // lo0 (>=), hi1 (<=), lo2 (>=)
__device__ int                 g_nwork;
__device__ int4                g_work[WLCAP];       // {sel, bin, start, cnt}
__device__ unsigned long long  g_scat[3][CAP];
__device__ int                 g_idx[3 * KMAX];
__device__ unsigned            g_arrive;
__device__ volatile unsigned   g_gen;

__device__ __forceinline__ unsigned fkey(float f) {
    unsigned u = __float_as_uint(f);
    return (u & 0x80000000u) ? ~u : (u | 0x80000000u);   // monotonic
}

// Generation-counter grid barrier. Safe: all BLKS blocks co-resident
// (__launch_bounds__(THR,2) -> >=304 resident blocks on 152 SMs).
__device__ __forceinline__ void grid_sync() {
    __syncthreads();
    if (threadIdx.x == 0) {
        unsigned gen = g_gen;
        __threadfence();                               // release
        if (atomicAdd(&g_arrive, 1u) == (unsigned)BLKS - 1u) {
            g_arrive = 0u;
            __threadfence();
            g_gen = gen + 1u;
        } else {
            while (g_gen == gen) __nanosleep(32);
            __threadfence();                           // acquire
        }
    }
    __syncthreads();
}

__global__ __launch_bounds__(THR, 2)
void fused_kernel(const float* __restrict__ h, const float4* __restrict__ A4,
                  const float* __restrict__ W, const float* __restrict__ bvec,
                  const int* __restrict__ bag, float* __restrict__ out,
                  int N, int D, int K) {
    __shared__ unsigned long long s_u64[SEGB];        // 8KB, aliased per phase
    unsigned* s_u32 = (unsigned*)s_u64;
    float*    s_f   = (float*)s_u64;

    const int tid = threadIdx.x;
    const int bid = blockIdx.x;
    const int bg  = __ldg(bag);
    const unsigned uK = (unsigned)K;
    const int N2 = N >> 1;                            // element pairs

    // ---- phase 1: histograms (2 elements per float4 load) ---------------------
    for (int i = bid * THR + tid; i < N2; i += BLKS * THR) {
        float4 a = A4[i];
        float v0  = bg ? a.y : a.x,  vo0 = bg ? a.x : a.y;
        float v1  = bg ? a.w : a.z,  vo1 = bg ? a.z : a.w;
        atomicAdd(&g_hist[0][fkey(v0)  >> SHIFT], 1u);
        atomicAdd(&g_hist[1][fkey(vo0) >> SHIFT], 1u);
        atomicAdd(&g_hist[0][fkey(v1)  >> SHIFT], 1u);
        atomicAdd(&g_hist[1][fkey(vo1) >> SHIFT], 1u);
    }
    if ((N & 1) && bid == 0 && tid == 0) {            // odd tail element
        const float2* A2 = (const float2*)A4;
        float2 a = A2[N - 1];
        float v = bg ? a.y : a.x, vo = bg ? a.x : a.y;
        atomicAdd(&g_hist[0][fkey(v)  >> SHIFT], 1u);
        atomicAdd(&g_hist[1][fkey(vo) >> SHIFT], 1u);
    }
    grid_sync();

    // ---- phase 2: per-chunk sums (blocks < NCHUNK; warp hh handles hist hh) ---
    if (bid < NCHUNK) {
        const int warp = tid >> 5, lane = tid & 31;
        if (warp < 2) {
            unsigned ss = g_hist[warp][bid * CH + lane] +
                          g_hist[warp][bid * CH + lane + 32];
            #pragma unroll
            for (int o = 16; o; o >>= 1) ss += __shfl_down_sync(0xFFFFFFFFu, ss, o);
            if (lane == 0) g_bsum[warp][bid] = ss;
        }
    }
    grid_sync();

    // ---- phase 3: per-chunk offset tables (redundant chunk-sum scan) ----------
    if (bid < NCHUNK) {
        #pragma unroll
        for (int hh = 0; hh < 2; hh++) {
            // every block scans all NCHUNK chunk sums (THR == NCHUNK)
            unsigned v = g_bsum[hh][tid];
            s_u32[tid] = v;
            __syncthreads();
            for (int off = 1; off < NCHUNK; off <<= 1) {
                unsigned w = (tid >= off) ? s_u32[tid - off] : 0u;
                __syncthreads();
                s_u32[tid] += w;
                __syncthreads();
            }
            const unsigned total   = s_u32[NCHUNK - 1];
            const unsigned choff   = s_u32[bid] - g_bsum[hh][bid];  // excl. offset of my chunk
            __syncthreads();

            // scan my chunk's 64 bins
            unsigned cnt = 0;
            if (tid < CH) { cnt = g_hist[hh][bid * CH + tid]; s_u32[tid] = cnt; }
            __syncthreads();
            for (int off = 1; off < CH; off <<= 1) {
                unsigned w = (tid < CH && tid >= off) ? s_u32[tid - off] : 0u;
                __syncthreads();
                if (tid < CH) s_u32[tid] += w;
                __syncthreads();
            }
            if (tid < CH) {
                const int b = bid * CH + tid;
                const unsigned incl = s_u32[tid] + choff;
                // top-K (sel0 from hist0, sel2 from hist1)
                const int selt = hh ? 2 : 0;
                const unsigned above = total - incl;
                g_base[selt][b] = (int)above;
                if (above < uK && cnt > 0) {
                    if (above + cnt >= uK) g_bin[selt] = (unsigned)b;
                    int w = atomicAdd(&g_nwork, 1);
                    if (w < WLCAP) g_work[w] = make_int4(selt, b, (int)above, (int)cnt);
                }
                // bottom-K (hist0 -> sel1)
                if (hh == 0) {
                    const unsigned below = incl - cnt;
                    g_base[1][b] = (int)below;
                    if (below < uK && cnt > 0) {
                        if (below + cnt >= uK) g_bin[1] = (unsigned)b;
                        int w = atomicAdd(&g_nwork, 1);
                        if (w < WLCAP) g_work[w] = make_int4(1, b, (int)below, (int)cnt);
                    }
                }
            }
            __syncthreads();
        }
    }
    grid_sync();

    // ---- phase 4: compact/scatter (2 elements per float4 load) ----------------
    {
        const unsigned lo0 = g_bin[0], hi1 = g_bin[1], lo2 = g_bin[2];
        for (int i = bid * THR + tid; i < N2; i += BLKS * THR) {
            float4 a = A4[i];
            #pragma unroll
            for (int e = 0; e < 2; e++) {
                float v  = e ? (bg ? a.w : a.z) : (bg ? a.y : a.x);
                float vo = e ? (bg ? a.z : a.w) : (bg ? a.x : a.y);
                const int idx = i * 2 + e;
                unsigned k0 = fkey(v), k2 = fkey(vo);
                unsigned b0 = k0 >> SHIFT, b2 = k2 >> SHIFT;
                unsigned long long il = (unsigned)(~(unsigned)idx);
                if (b0 >= lo0) {
                    int p = atomicAdd(&g_base[0][b0], 1);
                    if (p < CAP) g_scat[0][p] = ((unsigned long long)k0 << 32) | il;
                }
                if (b0 <= hi1) {
                    int p = atomicAdd(&g_base[1][b0], 1);
                    if (p < CAP) g_scat[1][p] = ((unsigned long long)(~k0) << 32) | il;
                }
                if (b2 >= lo2) {
                    int p = atomicAdd(&g_base[2][b2], 1);
                    if (p < CAP) g_scat[2][p] = ((unsigned long long)k2 << 32) | il;
                }
            }
        }
        if ((N & 1) && bid == 0 && tid == 0) {
            const float2* A2 = (const float2*)A4;
            float2 a = A2[N - 1];
            float v = bg ? a.y : a.x, vo = bg ? a.x : a.y;
            unsigned k0 = fkey(v), k2 = fkey(vo);
            unsigned b0 = k0 >> SHIFT, b2 = k2 >> SHIFT;
            unsigned long long il = (unsigned)(~(unsigned)(N - 1));
            if (b0 >= lo0) {
                int p = atomicAdd(&g_base[0][b0], 1);
                if (p < CAP) g_scat[0][p] = ((unsigned long long)k0 << 32) | il;
            }
            if (b0 <= hi1) {
                int p = atomicAdd(&g_base[1][b0], 1);
                if (p < CAP) g_scat[1][p] = ((unsigned long long)(~k0) << 32) | il;
            }
            if (b2 >= lo2) {
                int p = atomicAdd(&g_base[2][b2], 1);
                if (p < CAP) g_scat[2][p] = ((unsigned long long)k2 << 32) | il;
            }
        }
    }
    grid_sync();

    // ---- phase 5: rank segments -------------------------------------------------
    {
        const int nwork = g_nwork < WLCAP ? g_nwork : WLCAP;
        for (int e = bid; e < nwork; e += BLKS) {
            int4 w = g_work[e];
            const int sel = w.x, start = w.z;
            int cnt = w.w;
            if (start + cnt > CAP) cnt = CAP - start;
            if (cnt > SEGB) cnt = SEGB;
            if (cnt <= 0) continue;
            const unsigned long long* seg = &g_scat[sel][start];

            if (cnt == 1) {
                if (tid == 0 && start < K)
                    g_idx[sel * K + start] = (int)(~(unsigned)(seg[0] & 0xFFFFFFFFull));
                continue;
            }
            for (int j = tid; j < cnt; j += THR) s_u64[j] = seg[j];
            __syncthreads();
            for (int i = tid; i < cnt; i += THR) {
                unsigned long long key = s_u64[i];
                int rank = 0;
                int j = 0;
                #pragma unroll 4
                for (; j + 3 < cnt; j += 4) {
                    rank += (s_u64[j]     > key);
                    rank += (s_u64[j + 1] > key);
                    rank += (s_u64[j + 2] > key);
                    rank += (s_u64[j + 3] > key);
                }
                for (; j < cnt; j++) rank += (s_u64[j] > key);
                int pos = start + rank;
                if (pos < K)
                    g_idx[sel * K + pos] = (int)(~(unsigned)(key & 0xFFFFFFFFull));
            }
            __syncthreads();
        }
    }
    grid_sync();

    // ---- phase 6: zero state + gemv/softmax (4 rows per warp) --------------------
    {
        uint4* hp = (uint4*)g_hist;
        const int totalw = 2 * NBINS / 4;
        for (int i = bid * THR + tid; i < totalw; i += BLKS * THR)
            hp[i] = make_uint4(0u, 0u, 0u, 0u);
        if (bid == 0 && tid == 0) g_nwork = 0;

        float* ws0 = s_f;            // [0,D): W[:,0]
        float* ws1 = s_f + D;        // [D,2D): W[:,1]
        for (int j = tid; j < D; j += THR) {
            ws0[j] = W[j * 2 + 0];
            ws1[j] = W[j * 2 + 1];
        }
        __syncthreads();
        const float4* w04 = (const float4*)ws0;
        const float4* w14 = (const float4*)ws1;

        const int warp = tid >> 5, lane = tid & 31;
        const int nwarps = BLKS * (THR >> 5);
        const int wgid = bid * (THR >> 5) + warp;
        const int total = 3 * K;
        const int nq = D >> 2;
        const float bb0 = bvec[0], bb1 = bvec[1];

        for (int rbase = wgid * 4; rbase < total; rbase += nwarps * 4) {
            const int i0 = g_idx[rbase];
            const int i1 = (rbase + 1 < total) ? g_idx[rbase + 1] : i0;
            const int i2 = (rbase + 2 < total) ? g_idx[rbase + 2] : i0;
            const int i3 = (rbase + 3 < total) ? g_idx[rbase + 3] : i0;
            const float4* p0 = (const float4*)(h + (size_t)i0 * D);
            const float4* p1 = (const float4*)(h + (size_t)i1 * D);
            const float4* p2 = (const float4*)(h + (size_t)i2 * D);
            const float4* p3 = (const float4*)(h + (size_t)i3 * D);

            float c00 = 0.f, c01 = 0.f, c10 = 0.f, c11 = 0.f;
            float c20 = 0.f, c21 = 0.f, c30 = 0.f, c31 = 0.f;

            int t = lane;
            for (; t + 32 < nq; t += 64) {
                float4 a0 = p0[t],      a1 = p1[t],      a2 = p2[t],      a3 = p3[t];
                float4 d0 = p0[t + 32], d1 = p1[t + 32], d2 = p2[t + 32], d3 = p3[t + 32];
                float4 w0 = w04[t],      w1 = w14[t];
                float4 e0 = w04[t + 32], e1 = w14[t + 32];
                c00 = fmaf(a0.x, w0.x, c00); c01 = fmaf(a0.x, w1.x, c01);
                c10 = fmaf(a1.x, w0.x, c10); c11 = fmaf(a1.x, w1.x, c11);
                c20 = fmaf(a2.x, w0.x, c20); c21 = fmaf(a2.x, w1.x, c21);
                c30 = fmaf(a3.x, w0.x, c30); c31 = fmaf(a3.x, w1.x, c31);
                c00 = fmaf(a0.y, w0.y, c00); c01 = fmaf(a0.y, w1.y, c01);
                c10 = fmaf(a1.y, w0.y, c10); c11 = fmaf(a1.y, w1.y, c11);
                c20 = fmaf(a2.y, w0.y, c20); c21 = fmaf(a2.y, w1.y, c21);
                c30 = fmaf(a3.y, w0.y, c30); c31 = fmaf(a3.y, w1.y, c31);
                c00 = fmaf(a0.z, w0.z, c00); c01 = fmaf(a0.z, w1.z, c01);
                c10 = fmaf(a1.z, w0.z, c10); c11 = fmaf(a1.z, w1.z, c11);
                c20 = fmaf(a2.z, w0.z, c20); c21 = fmaf(a2.z, w1.z, c21);
                c30 = fmaf(a3.z, w0.z, c30); c31 = fmaf(a3.z, w1.z, c31);
                c00 = fmaf(a0.w, w0.w, c00); c01 = fmaf(a0.w, w1.w, c01);
                c10 = fmaf(a1.w, w0.w, c10); c11 = fmaf(a1.w, w1.w, c11);
                c20 = fmaf(a2.w, w0.w, c20); c21 = fmaf(a2.w, w1.w, c21);
                c30 = fmaf(a3.w, w0.w, c30); c31 = fmaf(a3.w, w1.w, c31);
                c00 = fmaf(d0.x, e0.x, c00); c01 = fmaf(d0.x, e1.x, c01);
                c10 = fmaf(d1.x, e0.x, c10); c11 = fmaf(d1.x, e1.x, c11);
                c20 = fmaf(d2.x, e0.x, c20); c21 = fmaf(d2.x, e1.x, c21);
                c30 = fmaf(d3.x, e0.x, c30); c31 = fmaf(d3.x, e1.x, c31);
                c00 = fmaf(d0.y, e0.y, c00); c01 = fmaf(d0.y, e1.y, c01);
                c10 = fmaf(d1.y, e0.y, c10); c11 = fmaf(d1.y, e1.y, c11);
                c20 = fmaf(d2.y, e0.y, c20); c21 = fmaf(d2.y, e1.y, c21);
                c30 = fmaf(d3.y, e0.y, c30); c31 = fmaf(d3.y, e1.y, c31);
                c00 = fmaf(d0.z, e0.z, c00); c01 = fmaf(d0.z, e1.z, c01);
                c10 = fmaf(d1.z, e0.z, c10); c11 = fmaf(d1.z, e1.z, c11);
                c20 = fmaf(d2.z, e0.z, c20); c21 = fmaf(d2.z, e1.z, c21);
                c30 = fmaf(d3.z, e0.z, c30); c31 = fmaf(d3.z, e1.z, c31);
                c00 = fmaf(d0.w, e0.w, c00); c01 = fmaf(d0.w, e1.w, c01);
                c10 = fmaf(d1.w, e0.w, c10); c11 = fmaf(d1.w, e1.w, c11);
                c20 = fmaf(d2.w, e0.w, c20); c21 = fmaf(d2.w, e1.w, c21);
                c30 = fmaf(d3.w, e0.w, c30); c31 = fmaf(d3.w, e1.w, c31);
            }
            for (; t < nq; t += 32) {
                float4 a0 = p0[t], a1 = p1[t], a2 = p2[t], a3 = p3[t];
                float4 w0 = w04[t], w1 = w14[t];
                c00 = fmaf(a0.x, w0.x, c00); c01 = fmaf(a0.x, w1.x, c01);
                c10 = fmaf(a1.x, w0.x, c10); c11 = fmaf(a1.x, w1.x, c11);
                c20 = fmaf(a2.x, w0.x, c20); c21 = fmaf(a2.x, w1.x, c21);
                c30 = fmaf(a3.x, w0.x, c30); c31 = fmaf(a3.x, w1.x, c31);
                c00 = fmaf(a0.y, w0.y, c00); c01 = fmaf(a0.y, w1.y, c01);
                c10 = fmaf(a1.y, w0.y, c10); c11 = fmaf(a1.y, w1.y, c11);
                c20 = fmaf(a2.y, w0.y, c20); c21 = fmaf(a2.y, w1.y, c21);
                c30 = fmaf(a3.y, w0.y, c30); c31 = fmaf(a3.y, w1.y, c31);
                c00 = fmaf(a0.z, w0.z, c00); c01 = fmaf(a0.z, w1.z, c01);
                c10 = fmaf(a1.z, w0.z, c10); c11 = fmaf(a1.z, w1.z, c11);
                c20 = fmaf(a2.z, w0.z, c20); c21 = fmaf(a2.z, w1.z, c21);
                c30 = fmaf(a3.z, w0.z, c30); c31 = fmaf(a3.z, w1.z, c31);
                c00 = fmaf(a0.w, w0.w, c00); c01 = fmaf(a0.w, w1.w, c01);
                c10 = fmaf(a1.w, w0.w, c10); c11 = fmaf(a1.w, w1.w, c11);
                c20 = fmaf(a2.w, w0.w, c20); c21 = fmaf(a2.w, w1.w, c21);
                c30 = fmaf(a3.w, w0.w, c30); c31 = fmaf(a3.w, w1.w, c31);
            }

            #pragma unroll
            for (int o = 16; o; o >>= 1) {
                c00 += __shfl_down_sync(0xFFFFFFFFu, c00, o);
                c01 += __shfl_down_sync(0xFFFFFFFFu, c01, o);
                c10 += __shfl_down_sync(0xFFFFFFFFu, c10, o);
                c11 += __shfl_down_sync(0xFFFFFFFFu, c11, o);
                c20 += __shfl_down_sync(0xFFFFFFFFu, c20, o);
                c21 += __shfl_down_sync(0xFFFFFFFFu, c21, o);
                c30 += __shfl_down_sync(0xFFFFFFFFu, c30, o);
                c31 += __shfl_down_sync(0xFFFFFFFFu, c31, o);
            }

            if (lane == 0) {
                float z0s[4] = {c00, c10, c20, c30};
                float z1s[4] = {c01, c11, c21, c31};
                #pragma unroll
                for (int q = 0; q < 4; q++) {
                    int r = rbase + q;
                    if (r >= total) break;
                    float z0 = z0s[q] + bb0, z1 = z1s[q] + bb1;
                    float m = fmaxf(z0, z1);
                    float e0 = expf(z0 - m), e1 = expf(z1 - m);
                    float inv = 1.0f / (e0 + e1);
                    out[r] = (r < K) ? 1.0f : 0.0f;
                    out[3 * K + r * 2 + 0] = z0;
                    out[3 * K + r * 2 + 1] = z1;
                    out[9 * K + r * 2 + 0] = e0 * inv;
                    out[9 * K + r * 2 + 1] = e1 * inv;
                }
            }
        }
    }
}

extern "C" void kernel_launch(void* const* d_in, const int* in_sizes, int n_in,
                              void* d_out, int out_size) {
    const float* h = (const float*)d_in[0];   // (N,1,D)
    const float* A = (const float*)d_in[1];   // (N,1,2)
    const float* W = (const float*)d_in[2];   // (D,2)
    const float* b = (const float*)d_in[3];   // (2,)
    const int* bag = (const int*)d_in[4];

    const int N = in_sizes[1] / 2;
    const int D = in_sizes[0] / N;
    int K = (int)(0.02 * (double)N);
    if (K == 0) K = 8;
    if (K > KMAX) K = KMAX;

    fused_kernel<<<BLKS, THR>>>(h, (const float4*)A, W, b, bag,
                                (float*)d_out, N, D, K);
}

// round 11
// speedup vs baseline: 5.6050x; 1.0089x over previous
#include <cuda_runtime.h>
#include <cuda_bf16.h>
#include <math.h>

// ---------------------------------------------------------------------------
// SINGLE-KERNEL fused pipeline (persistent grid + device grid barriers).
// 3x exact top-K over columns of A (N x 2), (value desc, index asc) = lax.top_k.
// 148 blocks x 512 threads (32 warps/SM resident => 2x latency hiding vs R10).
// Phases (5 grid barriers):
//   1 hist    : 16384-bin histograms of fkey(v), fkey(vo)  (float4, 2 elem/thr)
//   2 bsum    : per-128-bin-chunk sums (128 chunks)
//   3 base    : each chunk-block scans chunk sums + its bins; offset tables,
//               thresholds, worklist (fat bins split into SUB=128-key entries)
//   4 compact : scatter candidates to final segment via atomicAdd(g_base)
//   5 rank    : one block per worklist entry, rank-by-comparison (keys unique)
//   6 gemv    : 2 rows/warp gather + 512->2 GEMV (smem W) + softmax; zero state
// State zero at module load; last phase re-zeroes => every call identical.
// Output (float32, 15K): [0,3K) labels | [3K,9K) logits | [9K,15K) softmax
// ---------------------------------------------------------------------------

#define NBINS   16384
#define SHIFT   18
#define NCHUNK  128
#define CH      128                // bins per chunk
#define SUB     128                // keys ranked per worklist entry
#define CAP     4096
#define KMAX    2048
#define SEGB    1024
#define WLCAP   8192
#define BLKS    148
#define THR     512

__device__ unsigned            g_hist[2][NBINS];
__device__ unsigned            g_bsum[2][NCHUNK];
__device__ int                 g_base[3][NBINS];
__device__ unsigned            g_bin[3];            // lo0 (>=), hi1 (<=), lo2 (>=)
__device__ int                 g_nwork;
__device__ int4                g_work[WLCAP];       // {sel|sub<<2, bin, start, cnt}
__device__ unsigned long long  g_scat[3][CAP];
__device__ int                 g_idx[3 * KMAX];
__device__ unsigned            g_arrive;
__device__ volatile unsigned   g_gen;

__device__ __forceinline__ unsigned fkey(float f) {
    unsigned u = __float_as_uint(f);
    return (u & 0x80000000u) ? ~u : (u | 0x80000000u);   // monotonic
}

// Generation-counter grid barrier. Safe: 148 blocks, >=296 resident slots.
__device__ __forceinline__ void grid_sync() {
    __syncthreads();
    if (threadIdx.x == 0) {
        unsigned gen = g_gen;
        __threadfence();                               // release
        if (atomicAdd(&g_arrive, 1u) == (unsigned)BLKS - 1u) {
            g_arrive = 0u;
            __threadfence();
            g_gen = gen + 1u;
        } else {
            while (g_gen == gen) __nanosleep(32);
            __threadfence();                           // acquire
        }
    }
    __syncthreads();
}

__global__ __launch_bounds__(THR, 2)
void fused_kernel(const float* __restrict__ h, const float4* __restrict__ A4,
                  const float* __restrict__ W, const float* __restrict__ bvec,
                  const int* __restrict__ bag, float* __restrict__ out,
                  int N, int D, int K) {
    __shared__ unsigned long long s_u64[SEGB];        // 8KB, aliased per phase
    unsigned* s_u32 = (unsigned*)s_u64;
    float*    s_f   = (float*)s_u64;

    const int tid = threadIdx.x;
    const int bid = blockIdx.x;
    const int bg  = __ldg(bag);
    const unsigned uK = (unsigned)K;
    const int N2 = N >> 1;

    // ---- phase 1: histograms (2 elements per float4 load) ---------------------
    for (int i = bid * THR + tid; i < N2; i += BLKS * THR) {
        float4 a = A4[i];
        float v0  = bg ? a.y : a.x,  vo0 = bg ? a.x : a.y;
        float v1  = bg ? a.w : a.z,  vo1 = bg ? a.z : a.w;
        atomicAdd(&g_hist[0][fkey(v0)  >> SHIFT], 1u);
        atomicAdd(&g_hist[1][fkey(vo0) >> SHIFT], 1u);
        atomicAdd(&g_hist[0][fkey(v1)  >> SHIFT], 1u);
        atomicAdd(&g_hist[1][fkey(vo1) >> SHIFT], 1u);
    }
    if ((N & 1) && bid == 0 && tid == 0) {
        const float2* A2 = (const float2*)A4;
        float2 a = A2[N - 1];
        float v = bg ? a.y : a.x, vo = bg ? a.x : a.y;
        atomicAdd(&g_hist[0][fkey(v)  >> SHIFT], 1u);
        atomicAdd(&g_hist[1][fkey(vo) >> SHIFT], 1u);
    }
    grid_sync();

    // ---- phase 2: per-chunk sums (blocks < NCHUNK) -----------------------------
    if (bid < NCHUNK) {
        // threads [0,128): hist0, [128,256): hist1; one bin per thread
        unsigned v = 0;
        if (tid < 256) {
            int hh = tid >> 7, j = tid & 127;
            v = g_hist[hh][bid * CH + j];
        }
        s_u32[tid < 256 ? tid : 256] = 0;             // (dummy slot for others)
        __syncthreads();
        if (tid < 256) s_u32[tid] = v;
        __syncthreads();
        for (int off = 64; off; off >>= 1) {
            if (tid < 256 && (tid & 127) < off) s_u32[tid] += s_u32[tid + off];
            __syncthreads();
        }
        if (tid == 0)   g_bsum[0][bid] = s_u32[0];
        if (tid == 128) g_bsum[1][bid] = s_u32[128];
    }
    grid_sync();

    // ---- phase 3: offset tables + thresholds + worklist (blocks < NCHUNK) ------
    if (bid < NCHUNK) {
        #pragma unroll
        for (int hh = 0; hh < 2; hh++) {
            // scan all NCHUNK chunk sums
            if (tid < NCHUNK) s_u32[tid] = g_bsum[hh][tid];
            __syncthreads();
            for (int off = 1; off < NCHUNK; off <<= 1) {
                unsigned w = (tid < NCHUNK && tid >= off) ? s_u32[tid - off] : 0u;
                __syncthreads();
                if (tid < NCHUNK) s_u32[tid] += w;
                __syncthreads();
            }
            const unsigned total = s_u32[NCHUNK - 1];
            const unsigned choff = s_u32[bid] - g_bsum[hh][bid];
            __syncthreads();

            // scan my chunk's CH bins
            unsigned cnt = 0;
            if (tid < CH) { cnt = g_hist[hh][bid * CH + tid]; s_u32[tid] = cnt; }
            __syncthreads();
            for (int off = 1; off < CH; off <<= 1) {
                unsigned w = (tid < CH && tid >= off) ? s_u32[tid - off] : 0u;
                __syncthreads();
                if (tid < CH) s_u32[tid] += w;
                __syncthreads();
            }
            if (tid < CH) {
                const int b = bid * CH + tid;
                const unsigned incl = s_u32[tid] + choff;
                // top-K (sel0 from hist0, sel2 from hist1)
                const int selt = hh ? 2 : 0;
                const unsigned above = total - incl;
                g_base[selt][b] = (int)above;
                if (above < uK && cnt > 0) {
                    if (above + cnt >= uK) g_bin[selt] = (unsigned)b;
                    for (int sub = 0; sub * SUB < (int)cnt; sub++) {
                        int w = atomicAdd(&g_nwork, 1);
                        if (w < WLCAP)
                            g_work[w] = make_int4(selt | (sub << 2), b, (int)above, (int)cnt);
                    }
                }
                // bottom-K (hist0 -> sel1)
                if (hh == 0) {
                    const unsigned below = incl - cnt;
                    g_base[1][b] = (int)below;
                    if (below < uK && cnt > 0) {
                        if (below + cnt >= uK) g_bin[1] = (unsigned)b;
                        for (int sub = 0; sub * SUB < (int)cnt; sub++) {
                            int w = atomicAdd(&g_nwork, 1);
                            if (w < WLCAP)
                                g_work[w] = make_int4(1 | (sub << 2), b, (int)below, (int)cnt);
                        }
                    }
                }
            }
            __syncthreads();
        }
    }
    grid_sync();

    // ---- phase 4: compact/scatter (2 elements per float4 load) -----------------
    {
        const unsigned lo0 = g_bin[0], hi1 = g_bin[1], lo2 = g_bin[2];
        for (int i = bid * THR + tid; i < N2; i += BLKS * THR) {
            float4 a = A4[i];
            #pragma unroll
            for (int e = 0; e < 2; e++) {
                float v  = e ? (bg ? a.w : a.z) : (bg ? a.y : a.x);
                float vo = e ? (bg ? a.z : a.w) : (bg ? a.x : a.y);
                const int idx = i * 2 + e;
                unsigned k0 = fkey(v), k2 = fkey(vo);
                unsigned b0 = k0 >> SHIFT, b2 = k2 >> SHIFT;
                unsigned long long il = (unsigned)(~(unsigned)idx);
                if (b0 >= lo0) {
                    int p = atomicAdd(&g_base[0][b0], 1);
                    if (p < CAP) g_scat[0][p] = ((unsigned long long)k0 << 32) | il;
                }
                if (b0 <= hi1) {
                    int p = atomicAdd(&g_base[1][b0], 1);
                    if (p < CAP) g_scat[1][p] = ((unsigned long long)(~k0) << 32) | il;
                }
                if (b2 >= lo2) {
                    int p = atomicAdd(&g_base[2][b2], 1);
                    if (p < CAP) g_scat[2][p] = ((unsigned long long)k2 << 32) | il;
                }
            }
        }
        if ((N & 1) && bid == 0 && tid == 0) {
            const float2* A2 = (const float2*)A4;
            float2 a = A2[N - 1];
            float v = bg ? a.y : a.x, vo = bg ? a.x : a.y;
            unsigned k0 = fkey(v), k2 = fkey(vo);
            unsigned b0 = k0 >> SHIFT, b2 = k2 >> SHIFT;
            unsigned long long il = (unsigned)(~(unsigned)(N - 1));
            if (b0 >= lo0) {
                int p = atomicAdd(&g_base[0][b0], 1);
                if (p < CAP) g_scat[0][p] = ((unsigned long long)k0 << 32) | il;
            }
            if (b0 <= hi1) {
                int p = atomicAdd(&g_base[1][b0], 1);
                if (p < CAP) g_scat[1][p] = ((unsigned long long)(~k0) << 32) | il;
            }
            if (b2 >= lo2) {
                int p = atomicAdd(&g_base[2][b2], 1);
                if (p < CAP) g_scat[2][p] = ((unsigned long long)k2 << 32) | il;
            }
        }
    }
    grid_sync();

    // ---- phase 5: rank worklist entries (SUB keys per entry) -------------------
    {
        const int nwork = g_nwork < WLCAP ? g_nwork : WLCAP;
        for (int e = bid; e < nwork; e += BLKS) {
            int4 w = g_work[e];
            const int sel = w.x & 3, sub = w.x >> 2;
            const int start = w.z;
            int cnt = w.w;
            if (start + cnt > CAP) cnt = CAP - start;
            if (cnt > SEGB) cnt = SEGB;
            const int lo = sub * SUB;
            int hi = lo + SUB; if (hi > cnt) hi = cnt;
            if (lo >= cnt) continue;
            const unsigned long long* seg = &g_scat[sel][start];

            if (cnt == 1) {
                if (tid == 0 && start < K)
                    g_idx[sel * K + start] = (int)(~(unsigned)(seg[0] & 0xFFFFFFFFull));
                continue;
            }
            for (int j = tid; j < cnt; j += THR) s_u64[j] = seg[j];
            __syncthreads();
            for (int i = lo + tid; i < hi; i += THR) {
                unsigned long long key = s_u64[i];
                int rank = 0;
                int j = 0;
                #pragma unroll 4
                for (; j + 3 < cnt; j += 4) {
                    rank += (s_u64[j]     > key);
                    rank += (s_u64[j + 1] > key);
                    rank += (s_u64[j + 2] > key);
                    rank += (s_u64[j + 3] > key);
                }
                for (; j < cnt; j++) rank += (s_u64[j] > key);
                int pos = start + rank;
                if (pos < K)
                    g_idx[sel * K + pos] = (int)(~(unsigned)(key & 0xFFFFFFFFull));
            }
            __syncthreads();
        }
    }
    grid_sync();

    // ---- phase 6: zero state + gemv/softmax (2 rows per warp) ------------------
    {
        uint4* hp = (uint4*)g_hist;
        const int totalw = 2 * NBINS / 4;
        for (int i = bid * THR + tid; i < totalw; i += BLKS * THR)
            hp[i] = make_uint4(0u, 0u, 0u, 0u);
        if (bid == 0 && tid == 0) g_nwork = 0;

        float* ws0 = s_f;            // [0,D): W[:,0]
        float* ws1 = s_f + D;        // [D,2D): W[:,1]
        for (int j = tid; j < D; j += THR) {
            ws0[j] = W[j * 2 + 0];
            ws1[j] = W[j * 2 + 1];
        }
        __syncthreads();
        const float4* w04 = (const float4*)ws0;
        const float4* w14 = (const float4*)ws1;

        const int warp = tid >> 5, lane = tid & 31;
        const int nwarps = BLKS * (THR >> 5);
        const int wgid = bid * (THR >> 5) + warp;
        const int total = 3 * K;
        const int nq = D >> 2;
        const float bb0 = bvec[0], bb1 = bvec[1];

        for (int rbase = wgid * 2; rbase < total; rbase += nwarps * 2) {
            const bool two = (rbase + 1 < total);
            const int ia = g_idx[rbase];
            const int ib = two ? g_idx[rbase + 1] : ia;
            const float4* pa = (const float4*)(h + (size_t)ia * D);
            const float4* pb = (const float4*)(h + (size_t)ib * D);

            float a0 = 0.f, a1 = 0.f, b0 = 0.f, b1 = 0.f;
            int t = lane;
            for (; t + 96 < nq; t += 128) {
                float4 va0 = pa[t];
                float4 va1 = pa[t + 32];
                float4 va2 = pa[t + 64];
                float4 va3 = pa[t + 96];
                float4 vb0 = pb[t];
                float4 vb1 = pb[t + 32];
                float4 vb2 = pb[t + 64];
                float4 vb3 = pb[t + 96];
                #pragma unroll
                for (int u = 0; u < 4; u++) {
                    float4 va = (u == 0) ? va0 : (u == 1) ? va1 : (u == 2) ? va2 : va3;
                    float4 vb = (u == 0) ? vb0 : (u == 1) ? vb1 : (u == 2) ? vb2 : vb3;
                    float4 w0 = w04[t + u * 32];
                    float4 w1 = w14[t + u * 32];
                    a0 = fmaf(va.x, w0.x, a0);  a1 = fmaf(va.x, w1.x, a1);
                    b0 = fmaf(vb.x, w0.x, b0);  b1 = fmaf(vb.x, w1.x, b1);
                    a0 = fmaf(va.y, w0.y, a0);  a1 = fmaf(va.y, w1.y, a1);
                    b0 = fmaf(vb.y, w0.y, b0);  b1 = fmaf(vb.y, w1.y, b1);
                    a0 = fmaf(va.z, w0.z, a0);  a1 = fmaf(va.z, w1.z, a1);
                    b0 = fmaf(vb.z, w0.z, b0);  b1 = fmaf(vb.z, w1.z, b1);
                    a0 = fmaf(va.w, w0.w, a0);  a1 = fmaf(va.w, w1.w, a1);
                    b0 = fmaf(vb.w, w0.w, b0);  b1 = fmaf(vb.w, w1.w, b1);
                }
            }
            for (; t < nq; t += 32) {
                float4 va = pa[t];
                float4 vb = pb[t];
                float4 w0 = w04[t];
                float4 w1 = w14[t];
                a0 = fmaf(va.x, w0.x, a0);  a1 = fmaf(va.x, w1.x, a1);
                b0 = fmaf(vb.x, w0.x, b0);  b1 = fmaf(vb.x, w1.x, b1);
                a0 = fmaf(va.y, w0.y, a0);  a1 = fmaf(va.y, w1.y, a1);
                b0 = fmaf(vb.y, w0.y, b0);  b1 = fmaf(vb.y, w1.y, b1);
                a0 = fmaf(va.z, w0.z, a0);  a1 = fmaf(va.z, w1.z, a1);
                b0 = fmaf(vb.z, w0.z, b0);  b1 = fmaf(vb.z, w1.z, b1);
                a0 = fmaf(va.w, w0.w, a0);  a1 = fmaf(va.w, w1.w, a1);
                b0 = fmaf(vb.w, w0.w, b0);  b1 = fmaf(vb.w, w1.w, b1);
            }
            #pragma unroll
            for (int o = 16; o; o >>= 1) {
                a0 += __shfl_down_sync(0xFFFFFFFFu, a0, o);
                a1 += __shfl_down_sync(0xFFFFFFFFu, a1, o);
                b0 += __shfl_down_sync(0xFFFFFFFFu, b0, o);
                b1 += __shfl_down_sync(0xFFFFFFFFu, b1, o);
            }
            if (lane == 0) {
                {
                    int r = rbase;
                    float z0 = a0 + bb0, z1 = a1 + bb1;
                    float m = fmaxf(z0, z1);
                    float e0 = expf(z0 - m), e1 = expf(z1 - m);
                    float inv = 1.0f / (e0 + e1);
                    out[r] = (r < K) ? 1.0f : 0.0f;
                    out[3 * K + r * 2 + 0] = z0;
                    out[3 * K + r * 2 + 1] = z1;
                    out[9 * K + r * 2 + 0] = e0 * inv;
                    out[9 * K + r * 2 + 1] = e1 * inv;
                }
                if (two) {
                    int r = rbase + 1;
                    float z0 = b0 + bb0, z1 = b1 + bb1;
                    float m = fmaxf(z0, z1);
                    float e0 = expf(z0 - m), e1 = expf(z1 - m);
                    float inv = 1.0f / (e0 + e1);
                    out[r] = (r < K) ? 1.0f : 0.0f;
                    out[3 * K + r * 2 + 0] = z0;
                    out[3 * K + r * 2 + 1] = z1;
                    out[9 * K + r * 2 + 0] = e0 * inv;
                    out[9 * K + r * 2 + 1] = e1 * inv;
                }
            }
        }
    }
}

extern "C" void kernel_launch(void* const* d_in, const int* in_sizes, int n_in,
                              void* d_out, int out_size) {
    const float* h = (const float*)d_in[0];   // (N,1,D)
    const float* A = (const float*)d_in[1];   // (N,1,2)
    const float* W = (const float*)d_in[2];   // (D,2)
    const float* b = (const float*)d_in[3];   // (2,)
    const int* bag = (const int*)d_in[4];

    const int N = in_sizes[1] / 2;
    const int D = in_sizes[0] / N;
    int K = (int)(0.02 * (double)N);
    if (K == 0) K = 8;
    if (K > KMAX) K = KMAX;

    fused_kernel<<<BLKS, THR>>>(h, (const float4*)A, W, b, bag,
                                (float*)d_out, N, D, K);
}